// round 7
// baseline (speedup 1.0000x reference)
#include <cuda_runtime.h>
#include <math.h>
#include <stdint.h>

// Problem constants
#define B_SZ 4
#define T_SZ 2048
#define C_SZ 1024
#define NH   16
#define HD   64
#define MTOK (B_SZ * T_SZ)
#define QKV_STRIDE (3 * C_SZ)

// Scratch (device globals — no allocations allowed)
__device__ float    g_qkv[(size_t)MTOK * QKV_STRIDE];   // 96 MB
__device__ float    g_y[(size_t)MTOK * C_SZ];           // 32 MB
__device__ uint32_t g_xt[(size_t)MTOK * C_SZ];          // 32 MB  (tf32 of x)
__device__ uint32_t g_yt[(size_t)MTOK * C_SZ];          // 32 MB  (tf32 of y)
__device__ uint32_t g_wat[(size_t)(3 * C_SZ) * C_SZ];   // 12 MB  (w_attn^T tf32, [N][K])
__device__ uint32_t g_wpt[(size_t)C_SZ * C_SZ];         // 4 MB   (w_proj^T tf32, [N][K])

// ---------------------------------------------------------------------------
// Helpers
// ---------------------------------------------------------------------------
__device__ __forceinline__ uint32_t f32_to_tf32(float x) {
    uint32_t u;
    asm("cvt.rna.tf32.f32 %0, %1;" : "=r"(u) : "f"(x));
    return u;
}

__device__ __forceinline__ void mma_tf32(float c[4],
    uint32_t a0, uint32_t a1, uint32_t a2, uint32_t a3,
    uint32_t b0, uint32_t b1)
{
    asm volatile(
        "mma.sync.aligned.m16n8k8.row.col.f32.tf32.tf32.f32 "
        "{%0,%1,%2,%3}, {%4,%5,%6,%7}, {%8,%9}, {%0,%1,%2,%3};"
        : "+f"(c[0]), "+f"(c[1]), "+f"(c[2]), "+f"(c[3])
        : "r"(a0), "r"(a1), "r"(a2), "r"(a3), "r"(b0), "r"(b1));
}

__device__ __forceinline__ void ldsm4(uint32_t r[4], uint32_t saddr) {
    asm volatile("ldmatrix.sync.aligned.m8n8.x4.shared.b16 {%0,%1,%2,%3}, [%4];"
                 : "=r"(r[0]), "=r"(r[1]), "=r"(r[2]), "=r"(r[3]) : "r"(saddr));
}

__device__ __forceinline__ uint32_t smem_u32(const void* p) {
    return (uint32_t)__cvta_generic_to_shared(p);
}

__device__ __forceinline__ void cp16s(uint32_t saddr, const void* g) {
    asm volatile("cp.async.cg.shared.global [%0], [%1], 16;" :: "r"(saddr), "l"(g));
}
#define CP_COMMIT() asm volatile("cp.async.commit_group;")

// ---------------------------------------------------------------------------
// Pre-pass: fp32 -> tf32(u32) elementwise (rna)
// ---------------------------------------------------------------------------
__global__ __launch_bounds__(256) void cvt_tf32_kernel(
    const float* __restrict__ src, uint32_t* __restrict__ dst)
{
    int i = (blockIdx.x * 256 + threadIdx.x) * 4;
    float4 v = *(const float4*)(src + i);
    uint4 o;
    o.x = f32_to_tf32(v.x);
    o.y = f32_to_tf32(v.y);
    o.z = f32_to_tf32(v.z);
    o.w = f32_to_tf32(v.w);
    *(uint4*)(dst + i) = o;
}

// ---------------------------------------------------------------------------
// Pre-pass: transpose+convert weights: src[K][N] fp32 -> dst[N][K] tf32
// ---------------------------------------------------------------------------
__global__ __launch_bounds__(256) void transpose_tf32_kernel(
    const float* __restrict__ src, uint32_t* __restrict__ dst, int K, int N)
{
    __shared__ uint32_t t[32][33];
    int n0 = blockIdx.x * 32, k0 = blockIdx.y * 32;
    int c = threadIdx.x & 31, r = threadIdx.x >> 5;  // 32 x 8
    #pragma unroll
    for (int i = 0; i < 4; i++)
        t[r + 8 * i][c] = f32_to_tf32(src[(size_t)(k0 + r + 8 * i) * N + n0 + c]);
    __syncthreads();
    #pragma unroll
    for (int i = 0; i < 4; i++)
        dst[(size_t)(n0 + r + 8 * i) * K + k0 + c] = t[c][r + 8 * i];
}

// ---------------------------------------------------------------------------
// TF32 GEMM (mma.sync): C[M,N] = At[M,K] @ Bt[N,K]^T + bias
//   At [M][K], Bt [N][K], both tf32 u32.  Tile 128x128, K-chunk 32.
//   256 threads = 8 warps, warp tile 32(m) x 64(n).
//   All fragments via ldmatrix; zero cvt / scalar LDS in the mainloop.
// ---------------------------------------------------------------------------
#define G_PAD 36
#define G_STAGE (2 * 128 * G_PAD)          // u32 units per stage (A + B)
#define G_SMEM_BYTES (2 * G_STAGE * 4)     // 73728

__global__ __launch_bounds__(256) void gemm_mma_kernel(
    const uint32_t* __restrict__ At, const uint32_t* __restrict__ Bt,
    const float* __restrict__ bias, float* __restrict__ C,
    int M, int N, int K)
{
    extern __shared__ uint32_t gsm[];
    const uint32_t gsm_sh = smem_u32(gsm);

    const int tid  = threadIdx.x;
    const int wid  = tid >> 5;
    const int lane = tid & 31;
    const int g    = lane >> 2;
    const int tig  = lane & 3;
    const int wm   = (wid & 3) * 32;
    const int wn   = (wid >> 2) * 64;

    const int bm = blockIdx.y * 128;
    const int bn = blockIdx.x * 128;

    // LDSM lane addresses
    const int arow = (lane & 7) + ((lane >> 3) & 1) * 8;
    const int acol = (lane >> 4) * 4;
    const int brow = (lane & 7) + (lane >> 4) * 8;
    const int bcol = ((lane >> 3) & 1) * 4;
    const uint32_t a_off = 4u * ((wm + arow) * G_PAD + acol);
    const uint32_t b_off = 4u * (128 * G_PAD + (wn + brow) * G_PAD + bcol);

    // copy coords: 1024 16B-chunks per operand, 4 per thread
    const int c_r = tid >> 3;        // 0..31, +32 per pass
    const int c_u = (tid & 7) * 4;   // u32 col

    float acc[2][8][4] = {};

    auto fill = [&](int s, int c) {
        uint32_t* As_ = gsm + s * G_STAGE;
        uint32_t* Bs_ = As_ + 128 * G_PAD;
        #pragma unroll
        for (int p = 0; p < 4; p++) {
            int r = c_r + 32 * p;
            cp16s(smem_u32(&As_[r * G_PAD + c_u]),
                  At + (size_t)(bm + r) * K + c * 32 + c_u);
            cp16s(smem_u32(&Bs_[r * G_PAD + c_u]),
                  Bt + (size_t)(bn + r) * K + c * 32 + c_u);
        }
        CP_COMMIT();
    };

    const int NC = K >> 5;
    fill(0, 0);

    for (int kt = 0; kt < NC; kt++) {
        if (kt + 1 < NC) {
            fill((kt + 1) & 1, kt + 1);
            asm volatile("cp.async.wait_group 1;");
        } else {
            asm volatile("cp.async.wait_group 0;");
        }
        __syncthreads();

        const uint32_t st = gsm_sh + 4u * ((kt & 1) * G_STAGE);
        const uint32_t aB = st + a_off;
        const uint32_t bB = st + b_off;

        #pragma unroll
        for (int kk = 0; kk < 32; kk += 8) {
            uint32_t af[2][4];
            ldsm4(af[0], aB + 4u * kk);
            ldsm4(af[1], aB + 4u * (16 * G_PAD + kk));
            #pragma unroll
            for (int p = 0; p < 4; p++) {
                uint32_t bq[4];
                ldsm4(bq, bB + 4u * (16 * p * G_PAD + kk));
                #pragma unroll
                for (int mi = 0; mi < 2; mi++) {
                    mma_tf32(acc[mi][2 * p],     af[mi][0], af[mi][1], af[mi][2], af[mi][3], bq[0], bq[1]);
                    mma_tf32(acc[mi][2 * p + 1], af[mi][0], af[mi][1], af[mi][2], af[mi][3], bq[2], bq[3]);
                }
            }
        }
        __syncthreads();
    }

    // epilogue
    #pragma unroll
    for (int ni = 0; ni < 8; ni++) {
        int col = bn + wn + 8 * ni + 2 * tig;
        float bx = bias[col], by = bias[col + 1];
        #pragma unroll
        for (int mi = 0; mi < 2; mi++) {
            int row0 = bm + wm + 16 * mi + g;
            float2 o0 = {acc[mi][ni][0] + bx, acc[mi][ni][1] + by};
            float2 o1 = {acc[mi][ni][2] + bx, acc[mi][ni][3] + by};
            *(float2*)(C + (size_t)row0 * N + col) = o0;
            *(float2*)(C + (size_t)(row0 + 8) * N + col) = o1;
        }
    }
}

// ---------------------------------------------------------------------------
// RoPE (unchanged)
// ---------------------------------------------------------------------------
__global__ __launch_bounds__(256) void rope_kernel(float* __restrict__ qkv)
{
    int idx = blockIdx.x * blockDim.x + threadIdx.x;
    int pair = idx & 31;
    int h    = (idx >> 5) & (NH - 1);
    int tok  = idx >> 9;
    int t    = tok & (T_SZ - 1);

    float invf = powf(10000.0f, -(float)pair / 32.0f);
    float ang = (float)t * invf;
    float s, c;
    sincosf(ang, &s, &c);

    size_t base = (size_t)tok * QKV_STRIDE + h * HD;
    float* q = qkv + base;
    float* k = qkv + base + C_SZ;

    float q1 = q[pair], q2 = q[pair + 32];
    q[pair]      = q1 * c - q2 * s;
    q[pair + 32] = q2 * c + q1 * s;
    float k1 = k[pair], k2 = k[pair + 32];
    k[pair]      = k1 * c - k2 * s;
    k[pair + 32] = k2 * c + k1 * s;
}

// ---------------------------------------------------------------------------
// TF32 flash attention (unchanged from round 5 — best passing config)
// ---------------------------------------------------------------------------
#define FA_PAD 68
#define FQ 0
#define FK (128 * FA_PAD)
#define FV (FK + 64 * FA_PAD)
#define FP (FV + 64 * FA_PAD)
#define FA_SMEM_U32 (FP + 128 * FA_PAD)
#define FA_SMEM_BYTES (FA_SMEM_U32 * 4)

__global__ __launch_bounds__(128) void flash_tf32_kernel(
    const float* __restrict__ qkv, float* __restrict__ y)
{
    extern __shared__ uint32_t fsm[];
    uint32_t* Qs = fsm + FQ;
    uint32_t* Ks = fsm + FK;
    uint32_t* Vt = fsm + FV;
    uint32_t* Ps = fsm + FP;
    const uint32_t fsm_sh = smem_u32(fsm);

    const int qt = blockIdx.x;
    const int h  = blockIdx.y;
    const int b  = blockIdx.z;
    const int tid  = threadIdx.x;
    const int w    = tid >> 5;
    const int lane = tid & 31;
    const int g    = lane >> 2;
    const int tig  = lane & 3;

    const int arow = (lane & 7) + ((lane >> 3) & 1) * 8;
    const int acol = (lane >> 4) * 4;
    const int brow = (lane & 7) + (lane >> 4) * 8;
    const int bcol = ((lane >> 3) & 1) * 4;

    const uint32_t aq_base = fsm_sh + 4u * (FQ + (32 * w + arow) * FA_PAD + acol);
    const uint32_t ap_base = fsm_sh + 4u * (FP + (32 * w + arow) * FA_PAD + acol);
    const uint32_t bk_base = fsm_sh + 4u * (FK + brow * FA_PAD + bcol);
    const uint32_t bv_base = fsm_sh + 4u * (FV + brow * FA_PAD + bcol);

    const float* qbase = qkv + (size_t)b * T_SZ * QKV_STRIDE + h * HD;
    const float* kbase = qbase + C_SZ;
    const float* vbase = qbase + 2 * C_SZ;

    {
        int r = tid >> 4, c = (tid & 15) * 4;
        #pragma unroll
        for (int p = 0; p < 16; p++) {
            int rr = r + 8 * p;
            float4 v = *(const float4*)(qbase + (size_t)(qt * 128 + rr) * QKV_STRIDE + c);
            uint32_t* dst = Qs + rr * FA_PAD + c;
            dst[0] = f32_to_tf32(v.x * 0.125f);
            dst[1] = f32_to_tf32(v.y * 0.125f);
            dst[2] = f32_to_tf32(v.z * 0.125f);
            dst[3] = f32_to_tf32(v.w * 0.125f);
        }
    }

    float m[2][2], l[2][2];
    #pragma unroll
    for (int mi = 0; mi < 2; mi++) {
        m[mi][0] = -INFINITY; m[mi][1] = -INFINITY;
        l[mi][0] = 0.0f;      l[mi][1] = 0.0f;
    }
    float o[2][8][4] = {};

    const int wrow_lo = qt * 128 + 32 * w;
    const int ktmax = 2 * qt + 1;

    for (int kt = 0; kt <= ktmax; kt++) {
        {
            int r = tid >> 4, c = (tid & 15) * 4;
            #pragma unroll
            for (int p = 0; p < 8; p++) {
                int rr = r + 8 * p;
                float4 v = *(const float4*)(kbase + (size_t)(kt * 64 + rr) * QKV_STRIDE + c);
                uint32_t* dst = Ks + rr * FA_PAD + c;
                dst[0] = f32_to_tf32(v.x);
                dst[1] = f32_to_tf32(v.y);
                dst[2] = f32_to_tf32(v.z);
                dst[3] = f32_to_tf32(v.w);
            }
        }
        {
            int r = tid >> 4, c = (tid & 15) * 4;
            #pragma unroll
            for (int p = 0; p < 8; p++) {
                int rr = r + 8 * p;
                float4 v = *(const float4*)(vbase + (size_t)(kt * 64 + rr) * QKV_STRIDE + c);
                Vt[(c + 0) * FA_PAD + rr] = f32_to_tf32(v.x);
                Vt[(c + 1) * FA_PAD + rr] = f32_to_tf32(v.y);
                Vt[(c + 2) * FA_PAD + rr] = f32_to_tf32(v.z);
                Vt[(c + 3) * FA_PAD + rr] = f32_to_tf32(v.w);
            }
        }
        __syncthreads();

        const bool active = (kt * 64 <= wrow_lo + 31);
        if (active) {
            float s[2][8][4] = {};
            #pragma unroll
            for (int kk = 0; kk < 64; kk += 8) {
                uint32_t af[2][4];
                ldsm4(af[0], aq_base + 4u * kk);
                ldsm4(af[1], aq_base + 4u * (16 * FA_PAD + kk));
                #pragma unroll
                for (int p = 0; p < 4; p++) {
                    uint32_t bq[4];
                    ldsm4(bq, bk_base + 4u * (16 * p * FA_PAD + kk));
                    #pragma unroll
                    for (int mi = 0; mi < 2; mi++) {
                        mma_tf32(s[mi][2 * p],     af[mi][0], af[mi][1], af[mi][2], af[mi][3], bq[0], bq[1]);
                        mma_tf32(s[mi][2 * p + 1], af[mi][0], af[mi][1], af[mi][2], af[mi][3], bq[2], bq[3]);
                    }
                }
            }

            if (kt * 64 + 63 > wrow_lo) {
                #pragma unroll
                for (int mi = 0; mi < 2; mi++) {
                    int row0 = wrow_lo + 16 * mi + g;
                    int row1 = row0 + 8;
                    #pragma unroll
                    for (int ni = 0; ni < 8; ni++) {
                        int col = kt * 64 + 8 * ni + 2 * tig;
                        if (col     > row0) s[mi][ni][0] = -INFINITY;
                        if (col + 1 > row0) s[mi][ni][1] = -INFINITY;
                        if (col     > row1) s[mi][ni][2] = -INFINITY;
                        if (col + 1 > row1) s[mi][ni][3] = -INFINITY;
                    }
                }
            }

            #pragma unroll
            for (int mi = 0; mi < 2; mi++) {
                float mx0 = s[mi][0][0], mx1 = s[mi][0][2];
                #pragma unroll
                for (int ni = 0; ni < 8; ni++) {
                    mx0 = fmaxf(mx0, fmaxf(s[mi][ni][0], s[mi][ni][1]));
                    mx1 = fmaxf(mx1, fmaxf(s[mi][ni][2], s[mi][ni][3]));
                }
                mx0 = fmaxf(mx0, __shfl_xor_sync(0xffffffffu, mx0, 1));
                mx0 = fmaxf(mx0, __shfl_xor_sync(0xffffffffu, mx0, 2));
                mx1 = fmaxf(mx1, __shfl_xor_sync(0xffffffffu, mx1, 1));
                mx1 = fmaxf(mx1, __shfl_xor_sync(0xffffffffu, mx1, 2));

                float mn0 = fmaxf(m[mi][0], mx0), mn1 = fmaxf(m[mi][1], mx1);
                float al0 = __expf(m[mi][0] - mn0), al1 = __expf(m[mi][1] - mn1);

                uint32_t* pw0 = Ps + (32 * w + 16 * mi + g) * FA_PAD + 2 * tig;
                uint32_t* pw1 = pw0 + 8 * FA_PAD;
                float r0 = 0.0f, r1 = 0.0f;
                #pragma unroll
                for (int ni = 0; ni < 8; ni++) {
                    float p0 = __expf(s[mi][ni][0] - mn0);
                    float p1 = __expf(s[mi][ni][1] - mn0);
                    float p2 = __expf(s[mi][ni][2] - mn1);
                    float p3 = __expf(s[mi][ni][3] - mn1);
                    r0 += p0 + p1;
                    r1 += p2 + p3;
                    pw0[8 * ni]     = f32_to_tf32(p0);
                    pw0[8 * ni + 1] = f32_to_tf32(p1);
                    pw1[8 * ni]     = f32_to_tf32(p2);
                    pw1[8 * ni + 1] = f32_to_tf32(p3);
                }
                r0 += __shfl_xor_sync(0xffffffffu, r0, 1);
                r0 += __shfl_xor_sync(0xffffffffu, r0, 2);
                r1 += __shfl_xor_sync(0xffffffffu, r1, 1);
                r1 += __shfl_xor_sync(0xffffffffu, r1, 2);

                l[mi][0] = l[mi][0] * al0 + r0;
                l[mi][1] = l[mi][1] * al1 + r1;
                m[mi][0] = mn0;
                m[mi][1] = mn1;

                #pragma unroll
                for (int ni = 0; ni < 8; ni++) {
                    o[mi][ni][0] *= al0; o[mi][ni][1] *= al0;
                    o[mi][ni][2] *= al1; o[mi][ni][3] *= al1;
                }
            }

            __syncwarp();

            #pragma unroll
            for (int kk = 0; kk < 64; kk += 8) {
                uint32_t af[2][4];
                ldsm4(af[0], ap_base + 4u * kk);
                ldsm4(af[1], ap_base + 4u * (16 * FA_PAD + kk));
                #pragma unroll
                for (int p = 0; p < 4; p++) {
                    uint32_t bq[4];
                    ldsm4(bq, bv_base + 4u * (16 * p * FA_PAD + kk));
                    #pragma unroll
                    for (int mi = 0; mi < 2; mi++) {
                        mma_tf32(o[mi][2 * p],     af[mi][0], af[mi][1], af[mi][2], af[mi][3], bq[0], bq[1]);
                        mma_tf32(o[mi][2 * p + 1], af[mi][0], af[mi][1], af[mi][2], af[mi][3], bq[2], bq[3]);
                    }
                }
            }
        }
        __syncthreads();
    }

    #pragma unroll
    for (int mi = 0; mi < 2; mi++) {
        float inv0 = 1.0f / l[mi][0], inv1 = 1.0f / l[mi][1];
        int row0 = qt * 128 + 32 * w + 16 * mi + g;
        int row1 = row0 + 8;
        #pragma unroll
        for (int ni = 0; ni < 8; ni++) {
            int col = h * HD + 8 * ni + 2 * tig;
            float2 o0 = {o[mi][ni][0] * inv0, o[mi][ni][1] * inv0};
            float2 o1 = {o[mi][ni][2] * inv1, o[mi][ni][3] * inv1};
            *(float2*)(y + ((size_t)b * T_SZ + row0) * C_SZ + col) = o0;
            *(float2*)(y + ((size_t)b * T_SZ + row1) * C_SZ + col) = o1;
        }
    }
}

// ---------------------------------------------------------------------------
// Launch
// ---------------------------------------------------------------------------
extern "C" void kernel_launch(void* const* d_in, const int* in_sizes, int n_in,
                              void* d_out, int out_size)
{
    const float* x      = (const float*)d_in[0];
    const float* w_attn = (const float*)d_in[1];
    const float* b_attn = (const float*)d_in[2];
    const float* w_proj = (const float*)d_in[3];
    const float* b_proj = (const float*)d_in[4];
    float* out = (float*)d_out;

    float *qkv = nullptr, *y = nullptr;
    uint32_t *xt = nullptr, *yt = nullptr, *wat = nullptr, *wpt = nullptr;
    cudaGetSymbolAddress((void**)&qkv, g_qkv);
    cudaGetSymbolAddress((void**)&y, g_y);
    cudaGetSymbolAddress((void**)&xt, g_xt);
    cudaGetSymbolAddress((void**)&yt, g_yt);
    cudaGetSymbolAddress((void**)&wat, g_wat);
    cudaGetSymbolAddress((void**)&wpt, g_wpt);

    cudaFuncSetAttribute(gemm_mma_kernel,
                         cudaFuncAttributeMaxDynamicSharedMemorySize, G_SMEM_BYTES);
    cudaFuncSetAttribute(flash_tf32_kernel,
                         cudaFuncAttributeMaxDynamicSharedMemorySize, FA_SMEM_BYTES);

    // 0) pre-pass: tf32 conversions + weight transposes
    cvt_tf32_kernel<<<(MTOK * C_SZ) / 1024, 256>>>(x, xt);
    {
        dim3 g1(3 * C_SZ / 32, C_SZ / 32);
        transpose_tf32_kernel<<<g1, 256>>>(w_attn, wat, C_SZ, 3 * C_SZ);
        dim3 g2(C_SZ / 32, C_SZ / 32);
        transpose_tf32_kernel<<<g2, 256>>>(w_proj, wpt, C_SZ, C_SZ);
    }

    // 1) qkv = x @ w_attn + b_attn
    {
        dim3 grid(3 * C_SZ / 128, MTOK / 128);
        gemm_mma_kernel<<<grid, 256, G_SMEM_BYTES>>>(xt, wat, b_attn, qkv,
                                                     MTOK, 3 * C_SZ, C_SZ);
    }
    // 2) RoPE
    {
        int total = MTOK * NH * 32;
        rope_kernel<<<total / 256, 256>>>(qkv);
    }
    // 3) flash attention
    {
        dim3 grid(T_SZ / 128, NH, B_SZ);
        flash_tf32_kernel<<<grid, 128, FA_SMEM_BYTES>>>(qkv, y);
    }
    // 4) proj: cvt y -> tf32, then GEMM
    cvt_tf32_kernel<<<(MTOK * C_SZ) / 1024, 256>>>(y, yt);
    {
        dim3 grid(C_SZ / 128, MTOK / 128);
        gemm_mma_kernel<<<grid, 256, G_SMEM_BYTES>>>(yt, wpt, b_proj, out,
                                                     MTOK, C_SZ, C_SZ);
    }
}

// round 8
// speedup vs baseline: 2.5326x; 2.5326x over previous
#include <cuda_runtime.h>
#include <cuda_fp16.h>
#include <math.h>
#include <stdint.h>

// Problem constants
#define B_SZ 4
#define T_SZ 2048
#define C_SZ 1024
#define NH   16
#define HD   64
#define MTOK (B_SZ * T_SZ)
#define QKV_STRIDE (3 * C_SZ)

// Scratch (device globals — no allocations allowed)
__device__ float g_qkv[(size_t)MTOK * QKV_STRIDE];   // 96 MB (fp32, RoPE in-place)
__device__ __half g_xh[(size_t)MTOK * C_SZ];         // 16 MB  x as fp16
__device__ __half g_yh[(size_t)MTOK * C_SZ];         // 16 MB  attention out as fp16
__device__ __half g_wah[(size_t)(3 * C_SZ) * C_SZ];  // 6 MB   w_attn^T fp16 [N][K]
__device__ __half g_wph[(size_t)C_SZ * C_SZ];        // 2 MB   w_proj^T fp16 [N][K]

// ---------------------------------------------------------------------------
// Helpers
// ---------------------------------------------------------------------------
__device__ __forceinline__ void mma_f16(float c[4],
    uint32_t a0, uint32_t a1, uint32_t a2, uint32_t a3,
    uint32_t b0, uint32_t b1)
{
    asm volatile(
        "mma.sync.aligned.m16n8k16.row.col.f32.f16.f16.f32 "
        "{%0,%1,%2,%3}, {%4,%5,%6,%7}, {%8,%9}, {%0,%1,%2,%3};"
        : "+f"(c[0]), "+f"(c[1]), "+f"(c[2]), "+f"(c[3])
        : "r"(a0), "r"(a1), "r"(a2), "r"(a3), "r"(b0), "r"(b1));
}

__device__ __forceinline__ void ldsm4(uint32_t r[4], uint32_t saddr) {
    asm volatile("ldmatrix.sync.aligned.m8n8.x4.shared.b16 {%0,%1,%2,%3}, [%4];"
                 : "=r"(r[0]), "=r"(r[1]), "=r"(r[2]), "=r"(r[3]) : "r"(saddr));
}

__device__ __forceinline__ uint32_t smem_u32(const void* p) {
    return (uint32_t)__cvta_generic_to_shared(p);
}

__device__ __forceinline__ void cp16s(uint32_t saddr, const void* g) {
    asm volatile("cp.async.cg.shared.global [%0], [%1], 16;" :: "r"(saddr), "l"(g));
}
#define CP_COMMIT() asm volatile("cp.async.commit_group;")

// ---------------------------------------------------------------------------
// Pre-pass: fp32 -> fp16 elementwise
// ---------------------------------------------------------------------------
__global__ __launch_bounds__(256) void cvt_half_kernel(
    const float* __restrict__ src, __half* __restrict__ dst)
{
    int i = (blockIdx.x * 256 + threadIdx.x) * 4;
    float4 v = *(const float4*)(src + i);
    half2 h0 = __floats2half2_rn(v.x, v.y);
    half2 h1 = __floats2half2_rn(v.z, v.w);
    *(half2*)(dst + i) = h0;
    *(half2*)(dst + i + 2) = h1;
}

// ---------------------------------------------------------------------------
// Pre-pass: transpose+convert weights: src[K][N] fp32 -> dst[N][K] fp16
// ---------------------------------------------------------------------------
__global__ __launch_bounds__(256) void transpose_half_kernel(
    const float* __restrict__ src, __half* __restrict__ dst, int K, int N)
{
    __shared__ __half t[32][34];
    int n0 = blockIdx.x * 32, k0 = blockIdx.y * 32;
    int c = threadIdx.x & 31, r = threadIdx.x >> 5;  // 32 x 8
    #pragma unroll
    for (int i = 0; i < 4; i++)
        t[r + 8 * i][c] = __float2half_rn(src[(size_t)(k0 + r + 8 * i) * N + n0 + c]);
    __syncthreads();
    #pragma unroll
    for (int i = 0; i < 4; i++)
        dst[(size_t)(n0 + r + 8 * i) * K + k0 + c] = t[c][r + 8 * i];
}

// ---------------------------------------------------------------------------
// FP16 GEMM (mma.sync m16n8k16): C[M,N] = Ah[M,K] @ Bh[N,K]^T + bias
//   Tile 128x128, K-chunk 32 halfs, 128 threads = 4 warps, warp tile 64x64.
//   Both operands via ldmatrix (b16-native), cp.async double-buffered.
//   PAD_G=40 halfs/row (80 B): r*80 mod 128 distinct for r=0..7 -> LDSM
//   conflict-free.
// ---------------------------------------------------------------------------
#define PAD_G 40
#define G_STAGE_H (2 * 128 * PAD_G)         // halfs per stage (A + B)
#define G_SMEM_BYTES (2 * G_STAGE_H * 2)    // 40960

__global__ __launch_bounds__(128) void gemm_f16_kernel(
    const __half* __restrict__ Ah, const __half* __restrict__ Bh,
    const float* __restrict__ bias, float* __restrict__ C,
    int M, int N, int K)
{
    extern __shared__ __half gsm[];
    const uint32_t gsm_sh = smem_u32(gsm);

    const int tid  = threadIdx.x;
    const int wid  = tid >> 5;
    const int lane = tid & 31;
    const int g    = lane >> 2;
    const int tig  = lane & 3;
    const int wm   = (wid & 1) * 64;
    const int wn   = (wid >> 1) * 64;

    const int bm = blockIdx.y * 128;
    const int bn = blockIdx.x * 128;

    // LDSM lane address components (halfs)
    const int arow = (lane & 7) + ((lane >> 3) & 1) * 8;
    const int acol = ((lane >> 4) & 1) * 8;
    const int brow = (lane & 7) + ((lane >> 4) & 1) * 8;
    const int bcol = ((lane >> 3) & 1) * 8;
    const uint32_t a_off = 2u * ((wm + arow) * PAD_G + acol);
    const uint32_t b_off = 2u * (128 * PAD_G + (wn + brow) * PAD_G + bcol);

    float acc[4][8][4] = {};

    // fill stage s with K-chunk c (A: 128x32 halfs, B: 128x32 halfs)
    auto fill = [&](int s, int c) {
        __half* As_ = gsm + s * G_STAGE_H;
        __half* Bs_ = As_ + 128 * PAD_G;
        #pragma unroll
        for (int p = 0; p < 4; p++) {
            int id = tid + 128 * p;
            int r = id >> 2, u = id & 3;
            cp16s(smem_u32(&As_[r * PAD_G + u * 8]),
                  Ah + (size_t)(bm + r) * K + c * 32 + u * 8);
            cp16s(smem_u32(&Bs_[r * PAD_G + u * 8]),
                  Bh + (size_t)(bn + r) * K + c * 32 + u * 8);
        }
        CP_COMMIT();
    };

    const int NC = K >> 5;
    fill(0, 0);

    for (int kt = 0; kt < NC; kt++) {
        if (kt + 1 < NC) {
            fill((kt + 1) & 1, kt + 1);
            asm volatile("cp.async.wait_group 1;");
        } else {
            asm volatile("cp.async.wait_group 0;");
        }
        __syncthreads();

        const uint32_t st = gsm_sh + 2u * ((kt & 1) * G_STAGE_H);
        const uint32_t aB = st + a_off;
        const uint32_t bB = st + b_off;

        #pragma unroll
        for (int kk = 0; kk < 32; kk += 16) {
            uint32_t af[4][4];
            #pragma unroll
            for (int mi = 0; mi < 4; mi++)
                ldsm4(af[mi], aB + 2u * (16 * mi * PAD_G + kk));
            #pragma unroll
            for (int p = 0; p < 4; p++) {
                uint32_t bq[4];
                ldsm4(bq, bB + 2u * (16 * p * PAD_G + kk));
                #pragma unroll
                for (int mi = 0; mi < 4; mi++) {
                    mma_f16(acc[mi][2 * p],     af[mi][0], af[mi][1], af[mi][2], af[mi][3], bq[0], bq[1]);
                    mma_f16(acc[mi][2 * p + 1], af[mi][0], af[mi][1], af[mi][2], af[mi][3], bq[2], bq[3]);
                }
            }
        }
        __syncthreads();
    }

    // epilogue: bias + fp32 store
    #pragma unroll
    for (int ni = 0; ni < 8; ni++) {
        int col = bn + wn + 8 * ni + 2 * tig;
        float bx = bias[col], by = bias[col + 1];
        #pragma unroll
        for (int mi = 0; mi < 4; mi++) {
            int row0 = bm + wm + 16 * mi + g;
            float2 o0 = {acc[mi][ni][0] + bx, acc[mi][ni][1] + by};
            float2 o1 = {acc[mi][ni][2] + bx, acc[mi][ni][3] + by};
            *(float2*)(C + (size_t)row0 * N + col) = o0;
            *(float2*)(C + (size_t)(row0 + 8) * N + col) = o1;
        }
    }
}

// ---------------------------------------------------------------------------
// RoPE (unchanged, fp32 in-place on qkv)
// ---------------------------------------------------------------------------
__global__ __launch_bounds__(256) void rope_kernel(float* __restrict__ qkv)
{
    int idx = blockIdx.x * blockDim.x + threadIdx.x;
    int pair = idx & 31;
    int h    = (idx >> 5) & (NH - 1);
    int tok  = idx >> 9;
    int t    = tok & (T_SZ - 1);

    float invf = powf(10000.0f, -(float)pair / 32.0f);
    float ang = (float)t * invf;
    float s, c;
    sincosf(ang, &s, &c);

    size_t base = (size_t)tok * QKV_STRIDE + h * HD;
    float* q = qkv + base;
    float* k = qkv + base + C_SZ;

    float q1 = q[pair], q2 = q[pair + 32];
    q[pair]      = q1 * c - q2 * s;
    q[pair + 32] = q2 * c + q1 * s;
    float k1 = k[pair], k2 = k[pair + 32];
    k[pair]      = k1 * c - k2 * s;
    k[pair + 32] = k2 * c + k1 * s;
}

// ---------------------------------------------------------------------------
// FP16 flash attention (causal). Round-5 structure: BM=128, 128 threads =
// 4 warps, warp tile 32 q-rows x 64 kv. mma m16n8k16, all operands fp16 in
// smem (PAD_H=72 halfs/row: r*144 mod 128 distinct -> LDSM conflict-free).
// Output y written directly as fp16.
// ---------------------------------------------------------------------------
#define PAD_H 72
#define FQH 0
#define FKH (128 * PAD_H)
#define FVH (FKH + 64 * PAD_H)
#define FPH (FVH + 64 * PAD_H)
#define FA_SMEM_H (FPH + 128 * PAD_H)
#define FA_SMEM_BYTES (FA_SMEM_H * 2)

__global__ __launch_bounds__(128) void flash_f16_kernel(
    const float* __restrict__ qkv, __half* __restrict__ yh)
{
    extern __shared__ __half fsm[];
    __half* Qs = fsm + FQH;
    __half* Ks = fsm + FKH;
    __half* Vt = fsm + FVH;
    __half* Ps = fsm + FPH;
    const uint32_t fsm_sh = smem_u32(fsm);

    const int qt = blockIdx.x;
    const int h  = blockIdx.y;
    const int b  = blockIdx.z;
    const int tid  = threadIdx.x;
    const int w    = tid >> 5;
    const int lane = tid & 31;
    const int g    = lane >> 2;
    const int tig  = lane & 3;

    // LDSM lane address components (halfs)
    const int arow = (lane & 7) + ((lane >> 3) & 1) * 8;
    const int acol = ((lane >> 4) & 1) * 8;
    const int brow = (lane & 7) + ((lane >> 4) & 1) * 8;
    const int bcol = ((lane >> 3) & 1) * 8;

    const uint32_t aq_base = fsm_sh + 2u * (FQH + (32 * w + arow) * PAD_H + acol);
    const uint32_t ap_base = fsm_sh + 2u * (FPH + (32 * w + arow) * PAD_H + acol);
    const uint32_t bk_base = fsm_sh + 2u * (FKH + brow * PAD_H + bcol);
    const uint32_t bv_base = fsm_sh + 2u * (FVH + brow * PAD_H + bcol);

    const float* qbase = qkv + (size_t)b * T_SZ * QKV_STRIDE + h * HD;
    const float* kbase = qbase + C_SZ;
    const float* vbase = qbase + 2 * C_SZ;

    // load Q (128x64), scale 1/8, fp16
    {
        int r = tid >> 4, c = (tid & 15) * 4;
        #pragma unroll
        for (int p = 0; p < 16; p++) {
            int rr = r + 8 * p;
            float4 v = *(const float4*)(qbase + (size_t)(qt * 128 + rr) * QKV_STRIDE + c);
            __half* dst = Qs + rr * PAD_H + c;
            *(half2*)(dst)     = __floats2half2_rn(v.x * 0.125f, v.y * 0.125f);
            *(half2*)(dst + 2) = __floats2half2_rn(v.z * 0.125f, v.w * 0.125f);
        }
    }

    float m[2][2], l[2][2];
    #pragma unroll
    for (int mi = 0; mi < 2; mi++) {
        m[mi][0] = -INFINITY; m[mi][1] = -INFINITY;
        l[mi][0] = 0.0f;      l[mi][1] = 0.0f;
    }
    float o[2][8][4] = {};

    const int wrow_lo = qt * 128 + 32 * w;
    const int ktmax = 2 * qt + 1;

    for (int kt = 0; kt <= ktmax; kt++) {
        // K tile (64x64) -> Ks[kv][d] fp16
        {
            int r = tid >> 4, c = (tid & 15) * 4;
            #pragma unroll
            for (int p = 0; p < 8; p++) {
                int rr = r + 8 * p;
                float4 v = *(const float4*)(kbase + (size_t)(kt * 64 + rr) * QKV_STRIDE + c);
                __half* dst = Ks + rr * PAD_H + c;
                *(half2*)(dst)     = __floats2half2_rn(v.x, v.y);
                *(half2*)(dst + 2) = __floats2half2_rn(v.z, v.w);
            }
        }
        // V tile transposed -> Vt[d][kv] fp16
        {
            int r = tid >> 4, c = (tid & 15) * 4;
            #pragma unroll
            for (int p = 0; p < 8; p++) {
                int rr = r + 8 * p;
                float4 v = *(const float4*)(vbase + (size_t)(kt * 64 + rr) * QKV_STRIDE + c);
                Vt[(c + 0) * PAD_H + rr] = __float2half_rn(v.x);
                Vt[(c + 1) * PAD_H + rr] = __float2half_rn(v.y);
                Vt[(c + 2) * PAD_H + rr] = __float2half_rn(v.z);
                Vt[(c + 3) * PAD_H + rr] = __float2half_rn(v.w);
            }
        }
        __syncthreads();

        const bool active = (kt * 64 <= wrow_lo + 31);
        if (active) {
            // S = Q @ K^T  (32x64 per warp), 4 k16 steps
            float s[2][8][4] = {};
            #pragma unroll
            for (int kk = 0; kk < 64; kk += 16) {
                uint32_t af[2][4];
                ldsm4(af[0], aq_base + 2u * kk);
                ldsm4(af[1], aq_base + 2u * (16 * PAD_H + kk));
                #pragma unroll
                for (int p = 0; p < 4; p++) {
                    uint32_t bq[4];
                    ldsm4(bq, bk_base + 2u * (16 * p * PAD_H + kk));
                    #pragma unroll
                    for (int mi = 0; mi < 2; mi++) {
                        mma_f16(s[mi][2 * p],     af[mi][0], af[mi][1], af[mi][2], af[mi][3], bq[0], bq[1]);
                        mma_f16(s[mi][2 * p + 1], af[mi][0], af[mi][1], af[mi][2], af[mi][3], bq[2], bq[3]);
                    }
                }
            }

            // causal mask
            if (kt * 64 + 63 > wrow_lo) {
                #pragma unroll
                for (int mi = 0; mi < 2; mi++) {
                    int row0 = wrow_lo + 16 * mi + g;
                    int row1 = row0 + 8;
                    #pragma unroll
                    for (int ni = 0; ni < 8; ni++) {
                        int col = kt * 64 + 8 * ni + 2 * tig;
                        if (col     > row0) s[mi][ni][0] = -INFINITY;
                        if (col + 1 > row0) s[mi][ni][1] = -INFINITY;
                        if (col     > row1) s[mi][ni][2] = -INFINITY;
                        if (col + 1 > row1) s[mi][ni][3] = -INFINITY;
                    }
                }
            }

            // online softmax per mi
            #pragma unroll
            for (int mi = 0; mi < 2; mi++) {
                float mx0 = s[mi][0][0], mx1 = s[mi][0][2];
                #pragma unroll
                for (int ni = 0; ni < 8; ni++) {
                    mx0 = fmaxf(mx0, fmaxf(s[mi][ni][0], s[mi][ni][1]));
                    mx1 = fmaxf(mx1, fmaxf(s[mi][ni][2], s[mi][ni][3]));
                }
                mx0 = fmaxf(mx0, __shfl_xor_sync(0xffffffffu, mx0, 1));
                mx0 = fmaxf(mx0, __shfl_xor_sync(0xffffffffu, mx0, 2));
                mx1 = fmaxf(mx1, __shfl_xor_sync(0xffffffffu, mx1, 1));
                mx1 = fmaxf(mx1, __shfl_xor_sync(0xffffffffu, mx1, 2));

                float mn0 = fmaxf(m[mi][0], mx0), mn1 = fmaxf(m[mi][1], mx1);
                float al0 = __expf(m[mi][0] - mn0), al1 = __expf(m[mi][1] - mn1);

                __half* pw0 = Ps + (32 * w + 16 * mi + g) * PAD_H + 2 * tig;
                __half* pw1 = pw0 + 8 * PAD_H;
                float r0 = 0.0f, r1 = 0.0f;
                #pragma unroll
                for (int ni = 0; ni < 8; ni++) {
                    float p0 = __expf(s[mi][ni][0] - mn0);
                    float p1 = __expf(s[mi][ni][1] - mn0);
                    float p2 = __expf(s[mi][ni][2] - mn1);
                    float p3 = __expf(s[mi][ni][3] - mn1);
                    r0 += p0 + p1;
                    r1 += p2 + p3;
                    *(half2*)(pw0 + 8 * ni) = __floats2half2_rn(p0, p1);
                    *(half2*)(pw1 + 8 * ni) = __floats2half2_rn(p2, p3);
                }
                r0 += __shfl_xor_sync(0xffffffffu, r0, 1);
                r0 += __shfl_xor_sync(0xffffffffu, r0, 2);
                r1 += __shfl_xor_sync(0xffffffffu, r1, 1);
                r1 += __shfl_xor_sync(0xffffffffu, r1, 2);

                l[mi][0] = l[mi][0] * al0 + r0;
                l[mi][1] = l[mi][1] * al1 + r1;
                m[mi][0] = mn0;
                m[mi][1] = mn1;

                #pragma unroll
                for (int ni = 0; ni < 8; ni++) {
                    o[mi][ni][0] *= al0; o[mi][ni][1] *= al0;
                    o[mi][ni][2] *= al1; o[mi][ni][3] *= al1;
                }
            }

            __syncwarp();

            // O += P @ V  (4 k16 steps over kv)
            #pragma unroll
            for (int kk = 0; kk < 64; kk += 16) {
                uint32_t af[2][4];
                ldsm4(af[0], ap_base + 2u * kk);
                ldsm4(af[1], ap_base + 2u * (16 * PAD_H + kk));
                #pragma unroll
                for (int p = 0; p < 4; p++) {
                    uint32_t bq[4];
                    ldsm4(bq, bv_base + 2u * (16 * p * PAD_H + kk));
                    #pragma unroll
                    for (int mi = 0; mi < 2; mi++) {
                        mma_f16(o[mi][2 * p],     af[mi][0], af[mi][1], af[mi][2], af[mi][3], bq[0], bq[1]);
                        mma_f16(o[mi][2 * p + 1], af[mi][0], af[mi][1], af[mi][2], af[mi][3], bq[2], bq[3]);
                    }
                }
            }
        }
        __syncthreads();
    }

    // epilogue: normalize, write y as fp16
    #pragma unroll
    for (int mi = 0; mi < 2; mi++) {
        float inv0 = 1.0f / l[mi][0], inv1 = 1.0f / l[mi][1];
        int row0 = qt * 128 + 32 * w + 16 * mi + g;
        int row1 = row0 + 8;
        #pragma unroll
        for (int ni = 0; ni < 8; ni++) {
            int col = h * HD + 8 * ni + 2 * tig;
            *(half2*)(yh + ((size_t)b * T_SZ + row0) * C_SZ + col) =
                __floats2half2_rn(o[mi][ni][0] * inv0, o[mi][ni][1] * inv0);
            *(half2*)(yh + ((size_t)b * T_SZ + row1) * C_SZ + col) =
                __floats2half2_rn(o[mi][ni][2] * inv1, o[mi][ni][3] * inv1);
        }
    }
}

// ---------------------------------------------------------------------------
// Launch
// ---------------------------------------------------------------------------
extern "C" void kernel_launch(void* const* d_in, const int* in_sizes, int n_in,
                              void* d_out, int out_size)
{
    const float* x      = (const float*)d_in[0];
    const float* w_attn = (const float*)d_in[1];
    const float* b_attn = (const float*)d_in[2];
    const float* w_proj = (const float*)d_in[3];
    const float* b_proj = (const float*)d_in[4];
    float* out = (float*)d_out;

    float* qkv = nullptr;
    __half *xh = nullptr, *yh = nullptr, *wah = nullptr, *wph = nullptr;
    cudaGetSymbolAddress((void**)&qkv, g_qkv);
    cudaGetSymbolAddress((void**)&xh, g_xh);
    cudaGetSymbolAddress((void**)&yh, g_yh);
    cudaGetSymbolAddress((void**)&wah, g_wah);
    cudaGetSymbolAddress((void**)&wph, g_wph);

    cudaFuncSetAttribute(gemm_f16_kernel,
                         cudaFuncAttributeMaxDynamicSharedMemorySize, G_SMEM_BYTES);
    cudaFuncSetAttribute(flash_f16_kernel,
                         cudaFuncAttributeMaxDynamicSharedMemorySize, FA_SMEM_BYTES);

    // 0) pre-pass: fp16 conversions + weight transposes
    cvt_half_kernel<<<(MTOK * C_SZ) / 1024, 256>>>(x, xh);
    {
        dim3 g1(3 * C_SZ / 32, C_SZ / 32);
        transpose_half_kernel<<<g1, 256>>>(w_attn, wah, C_SZ, 3 * C_SZ);
        dim3 g2(C_SZ / 32, C_SZ / 32);
        transpose_half_kernel<<<g2, 256>>>(w_proj, wph, C_SZ, C_SZ);
    }

    // 1) qkv = x @ w_attn + b_attn   (fp32 out for RoPE)
    {
        dim3 grid(3 * C_SZ / 128, MTOK / 128);
        gemm_f16_kernel<<<grid, 128, G_SMEM_BYTES>>>(xh, wah, b_attn, qkv,
                                                     MTOK, 3 * C_SZ, C_SZ);
    }
    // 2) RoPE (fp32 in-place)
    {
        int total = MTOK * NH * 32;
        rope_kernel<<<total / 256, 256>>>(qkv);
    }
    // 3) flash attention -> y fp16
    {
        dim3 grid(T_SZ / 128, NH, B_SZ);
        flash_f16_kernel<<<grid, 128, FA_SMEM_BYTES>>>(qkv, yh);
    }
    // 4) out = y @ w_proj + b_proj
    {
        dim3 grid(C_SZ / 128, MTOK / 128);
        gemm_f16_kernel<<<grid, 128, G_SMEM_BYTES>>>(yh, wph, b_proj, out,
                                                     MTOK, C_SZ, C_SZ);
    }
}

// round 9
// speedup vs baseline: 3.0299x; 1.1963x over previous
#include <cuda_runtime.h>
#include <cuda_fp16.h>
#include <math.h>
#include <stdint.h>

// Problem constants
#define B_SZ 4
#define T_SZ 2048
#define C_SZ 1024
#define NH   16
#define HD   64
#define MTOK (B_SZ * T_SZ)
#define QKV_STRIDE (3 * C_SZ)

// Scratch (device globals — no allocations allowed)
__device__ __half g_qkvh[(size_t)MTOK * QKV_STRIDE]; // 48 MB (fp16, RoPE in-place)
__device__ __half g_xh[(size_t)MTOK * C_SZ];         // 16 MB  x as fp16
__device__ __half g_yh[(size_t)MTOK * C_SZ];         // 16 MB  attention out fp16
__device__ __half g_wah[(size_t)(3 * C_SZ) * C_SZ];  // 6 MB   w_attn^T fp16 [N][K]
__device__ __half g_wph[(size_t)C_SZ * C_SZ];        // 2 MB   w_proj^T fp16 [N][K]

// ---------------------------------------------------------------------------
// Helpers
// ---------------------------------------------------------------------------
__device__ __forceinline__ void mma_f16(float c[4],
    uint32_t a0, uint32_t a1, uint32_t a2, uint32_t a3,
    uint32_t b0, uint32_t b1)
{
    asm volatile(
        "mma.sync.aligned.m16n8k16.row.col.f32.f16.f16.f32 "
        "{%0,%1,%2,%3}, {%4,%5,%6,%7}, {%8,%9}, {%0,%1,%2,%3};"
        : "+f"(c[0]), "+f"(c[1]), "+f"(c[2]), "+f"(c[3])
        : "r"(a0), "r"(a1), "r"(a2), "r"(a3), "r"(b0), "r"(b1));
}

__device__ __forceinline__ void ldsm4(uint32_t r[4], uint32_t saddr) {
    asm volatile("ldmatrix.sync.aligned.m8n8.x4.shared.b16 {%0,%1,%2,%3}, [%4];"
                 : "=r"(r[0]), "=r"(r[1]), "=r"(r[2]), "=r"(r[3]) : "r"(saddr));
}

__device__ __forceinline__ void ldsm4t(uint32_t r[4], uint32_t saddr) {
    asm volatile("ldmatrix.sync.aligned.m8n8.x4.trans.shared.b16 {%0,%1,%2,%3}, [%4];"
                 : "=r"(r[0]), "=r"(r[1]), "=r"(r[2]), "=r"(r[3]) : "r"(saddr));
}

__device__ __forceinline__ uint32_t smem_u32(const void* p) {
    return (uint32_t)__cvta_generic_to_shared(p);
}

__device__ __forceinline__ void cp16s(uint32_t saddr, const void* g) {
    asm volatile("cp.async.cg.shared.global [%0], [%1], 16;" :: "r"(saddr), "l"(g));
}
#define CP_COMMIT() asm volatile("cp.async.commit_group;")

// ---------------------------------------------------------------------------
// Pre-pass: fp32 -> fp16 elementwise
// ---------------------------------------------------------------------------
__global__ __launch_bounds__(256) void cvt_half_kernel(
    const float* __restrict__ src, __half* __restrict__ dst)
{
    int i = (blockIdx.x * 256 + threadIdx.x) * 4;
    float4 v = *(const float4*)(src + i);
    *(half2*)(dst + i)     = __floats2half2_rn(v.x, v.y);
    *(half2*)(dst + i + 2) = __floats2half2_rn(v.z, v.w);
}

// ---------------------------------------------------------------------------
// Pre-pass: transpose+convert weights: src[K][N] fp32 -> dst[N][K] fp16
// ---------------------------------------------------------------------------
__global__ __launch_bounds__(256) void transpose_half_kernel(
    const float* __restrict__ src, __half* __restrict__ dst, int K, int N)
{
    __shared__ __half t[32][34];
    int n0 = blockIdx.x * 32, k0 = blockIdx.y * 32;
    int c = threadIdx.x & 31, r = threadIdx.x >> 5;  // 32 x 8
    #pragma unroll
    for (int i = 0; i < 4; i++)
        t[r + 8 * i][c] = __float2half_rn(src[(size_t)(k0 + r + 8 * i) * N + n0 + c]);
    __syncthreads();
    #pragma unroll
    for (int i = 0; i < 4; i++)
        dst[(size_t)(n0 + r + 8 * i) * K + k0 + c] = t[c][r + 8 * i];
}

// ---------------------------------------------------------------------------
// FP16 GEMM (mma.sync m16n8k16): C[M,N] = Ah[M,K] @ Bh[N,K]^T + bias
//   Templated output type (float for proj out, __half for qkv).
// ---------------------------------------------------------------------------
#define PAD_G 40
#define G_STAGE_H (2 * 128 * PAD_G)
#define G_SMEM_BYTES (2 * G_STAGE_H * 2)    // 40960

template <typename OutT>
__global__ __launch_bounds__(128) void gemm_f16_kernel(
    const __half* __restrict__ Ah, const __half* __restrict__ Bh,
    const float* __restrict__ bias, OutT* __restrict__ C,
    int M, int N, int K)
{
    extern __shared__ __half gsm[];
    const uint32_t gsm_sh = smem_u32(gsm);

    const int tid  = threadIdx.x;
    const int wid  = tid >> 5;
    const int lane = tid & 31;
    const int g    = lane >> 2;
    const int tig  = lane & 3;
    const int wm   = (wid & 1) * 64;
    const int wn   = (wid >> 1) * 64;

    const int bm = blockIdx.y * 128;
    const int bn = blockIdx.x * 128;

    const int arow = (lane & 7) + ((lane >> 3) & 1) * 8;
    const int acol = ((lane >> 4) & 1) * 8;
    const int brow = (lane & 7) + ((lane >> 4) & 1) * 8;
    const int bcol = ((lane >> 3) & 1) * 8;
    const uint32_t a_off = 2u * ((wm + arow) * PAD_G + acol);
    const uint32_t b_off = 2u * (128 * PAD_G + (wn + brow) * PAD_G + bcol);

    float acc[4][8][4] = {};

    auto fill = [&](int s, int c) {
        __half* As_ = gsm + s * G_STAGE_H;
        __half* Bs_ = As_ + 128 * PAD_G;
        #pragma unroll
        for (int p = 0; p < 4; p++) {
            int id = tid + 128 * p;
            int r = id >> 2, u = id & 3;
            cp16s(smem_u32(&As_[r * PAD_G + u * 8]),
                  Ah + (size_t)(bm + r) * K + c * 32 + u * 8);
            cp16s(smem_u32(&Bs_[r * PAD_G + u * 8]),
                  Bh + (size_t)(bn + r) * K + c * 32 + u * 8);
        }
        CP_COMMIT();
    };

    const int NC = K >> 5;
    fill(0, 0);

    for (int kt = 0; kt < NC; kt++) {
        if (kt + 1 < NC) {
            fill((kt + 1) & 1, kt + 1);
            asm volatile("cp.async.wait_group 1;");
        } else {
            asm volatile("cp.async.wait_group 0;");
        }
        __syncthreads();

        const uint32_t st = gsm_sh + 2u * ((kt & 1) * G_STAGE_H);
        const uint32_t aB = st + a_off;
        const uint32_t bB = st + b_off;

        #pragma unroll
        for (int kk = 0; kk < 32; kk += 16) {
            uint32_t af[4][4];
            #pragma unroll
            for (int mi = 0; mi < 4; mi++)
                ldsm4(af[mi], aB + 2u * (16 * mi * PAD_G + kk));
            #pragma unroll
            for (int p = 0; p < 4; p++) {
                uint32_t bq[4];
                ldsm4(bq, bB + 2u * (16 * p * PAD_G + kk));
                #pragma unroll
                for (int mi = 0; mi < 4; mi++) {
                    mma_f16(acc[mi][2 * p],     af[mi][0], af[mi][1], af[mi][2], af[mi][3], bq[0], bq[1]);
                    mma_f16(acc[mi][2 * p + 1], af[mi][0], af[mi][1], af[mi][2], af[mi][3], bq[2], bq[3]);
                }
            }
        }
        __syncthreads();
    }

    // epilogue: bias + store (fp32 or fp16)
    #pragma unroll
    for (int ni = 0; ni < 8; ni++) {
        int col = bn + wn + 8 * ni + 2 * tig;
        float bx = bias[col], by = bias[col + 1];
        #pragma unroll
        for (int mi = 0; mi < 4; mi++) {
            int row0 = bm + wm + 16 * mi + g;
            if constexpr (sizeof(OutT) == 4) {
                float2 o0 = {acc[mi][ni][0] + bx, acc[mi][ni][1] + by};
                float2 o1 = {acc[mi][ni][2] + bx, acc[mi][ni][3] + by};
                *(float2*)((float*)C + (size_t)row0 * N + col) = o0;
                *(float2*)((float*)C + (size_t)(row0 + 8) * N + col) = o1;
            } else {
                *(half2*)((__half*)C + (size_t)row0 * N + col) =
                    __floats2half2_rn(acc[mi][ni][0] + bx, acc[mi][ni][1] + by);
                *(half2*)((__half*)C + (size_t)(row0 + 8) * N + col) =
                    __floats2half2_rn(acc[mi][ni][2] + bx, acc[mi][ni][3] + by);
            }
        }
    }
}

// ---------------------------------------------------------------------------
// RoPE on fp16 qkv (fp32 math inside)
// ---------------------------------------------------------------------------
__global__ __launch_bounds__(256) void rope_half_kernel(__half* __restrict__ qkv)
{
    int idx = blockIdx.x * blockDim.x + threadIdx.x;
    int pair = idx & 31;
    int h    = (idx >> 5) & (NH - 1);
    int tok  = idx >> 9;
    int t    = tok & (T_SZ - 1);

    float invf = powf(10000.0f, -(float)pair / 32.0f);
    float ang = (float)t * invf;
    float s, c;
    sincosf(ang, &s, &c);

    size_t base = (size_t)tok * QKV_STRIDE + h * HD;
    __half* q = qkv + base;
    __half* k = qkv + base + C_SZ;

    float q1 = __half2float(q[pair]), q2 = __half2float(q[pair + 32]);
    q[pair]      = __float2half_rn(q1 * c - q2 * s);
    q[pair + 32] = __float2half_rn(q2 * c + q1 * s);
    float k1 = __half2float(k[pair]), k2 = __half2float(k[pair + 32]);
    k[pair]      = __float2half_rn(k1 * c - k2 * s);
    k[pair + 32] = __float2half_rn(k2 * c + k1 * s);
}

// ---------------------------------------------------------------------------
// FP16 flash attention (causal). BM=128, 128 threads = 4 warps, warp tile
// 32 q-rows x 64 kv. All tile loads cp.async from fp16 qkv; K/V double-
// buffered. V stored [kv][d]; PV B-fragments via ldmatrix.trans.
// Q loaded unscaled; 1/8 folded into S post-MMA.
// ---------------------------------------------------------------------------
#define PAD_H 72
#define KV_TILE_H (64 * PAD_H)
#define FQH 0
#define FKH (128 * PAD_H)                  // 2 stages: FKH + s*KV_TILE_H
#define FVH (FKH + 2 * KV_TILE_H)          // 2 stages
#define FPH (FVH + 2 * KV_TILE_H)
#define FA_SMEM_H (FPH + 128 * PAD_H)
#define FA_SMEM_BYTES (FA_SMEM_H * 2)      // 73728

__global__ __launch_bounds__(128) void flash_f16_kernel(
    const __half* __restrict__ qkv, __half* __restrict__ yh)
{
    extern __shared__ __half fsm[];
    __half* Ps = fsm + FPH;
    const uint32_t fsm_sh = smem_u32(fsm);

    const int qt = blockIdx.x;
    const int h  = blockIdx.y;
    const int b  = blockIdx.z;
    const int tid  = threadIdx.x;
    const int w    = tid >> 5;
    const int lane = tid & 31;
    const int g    = lane >> 2;
    const int tig  = lane & 3;

    // LDSM lane components
    const int arow = (lane & 7) + ((lane >> 3) & 1) * 8;
    const int acol = ((lane >> 4) & 1) * 8;
    const int brow = (lane & 7) + ((lane >> 4) & 1) * 8;   // non-trans (K)
    const int bcol = ((lane >> 3) & 1) * 8;
    const int vrow = (lane & 7) + ((lane >> 3) & 1) * 8;   // trans (V): bit3 -> k+8
    const int vcol = ((lane >> 4) & 1) * 8;                // bit4 -> n+8

    const uint32_t aq_base = fsm_sh + 2u * (FQH + (32 * w + arow) * PAD_H + acol);
    const uint32_t ap_base = fsm_sh + 2u * (FPH + (32 * w + arow) * PAD_H + acol);
    const uint32_t bk_base = fsm_sh + 2u * (FKH + brow * PAD_H + bcol);
    const uint32_t bv_base = fsm_sh + 2u * (FVH + vrow * PAD_H + vcol);

    const __half* qbase = qkv + (size_t)b * T_SZ * QKV_STRIDE + h * HD;
    const __half* kbase = qbase + C_SZ;
    const __half* vbase = qbase + 2 * C_SZ;

    // K/V tile fill via cp.async into stage s
    auto fill_kv = [&](int s, int kt) {
        __half* Kd = fsm + FKH + s * KV_TILE_H;
        __half* Vd = fsm + FVH + s * KV_TILE_H;
        #pragma unroll
        for (int p = 0; p < 4; p++) {
            int id = tid + 128 * p;
            int r = id >> 3, u = id & 7;
            cp16s(smem_u32(&Kd[r * PAD_H + u * 8]),
                  kbase + (size_t)(kt * 64 + r) * QKV_STRIDE + u * 8);
            cp16s(smem_u32(&Vd[r * PAD_H + u * 8]),
                  vbase + (size_t)(kt * 64 + r) * QKV_STRIDE + u * 8);
        }
        CP_COMMIT();
    };

    // Q tile (128x64) via cp.async, then KV stage 0, one group
    {
        __half* Qd = fsm + FQH;
        #pragma unroll
        for (int p = 0; p < 8; p++) {
            int id = tid + 128 * p;
            int r = id >> 3, u = id & 7;
            cp16s(smem_u32(&Qd[r * PAD_H + u * 8]),
                  qbase + (size_t)(qt * 128 + r) * QKV_STRIDE + u * 8);
        }
    }
    fill_kv(0, 0);

    float m[2][2], l[2][2];
    #pragma unroll
    for (int mi = 0; mi < 2; mi++) {
        m[mi][0] = -INFINITY; m[mi][1] = -INFINITY;
        l[mi][0] = 0.0f;      l[mi][1] = 0.0f;
    }
    float o[2][8][4] = {};

    const int wrow_lo = qt * 128 + 32 * w;
    const int ktmax = 2 * qt + 1;

    for (int kt = 0; kt <= ktmax; kt++) {
        const int s = kt & 1;
        if (kt < ktmax) {
            fill_kv(s ^ 1, kt + 1);
            asm volatile("cp.async.wait_group 1;");
        } else {
            asm volatile("cp.async.wait_group 0;");
        }
        __syncthreads();

        const bool active = (kt * 64 <= wrow_lo + 31);
        if (active) {
            const uint32_t bkS = bk_base + 2u * (s * KV_TILE_H);
            const uint32_t bvS = bv_base + 2u * (s * KV_TILE_H);

            // S = Q @ K^T  (unscaled)
            float sv[2][8][4] = {};
            #pragma unroll
            for (int kk = 0; kk < 64; kk += 16) {
                uint32_t af[2][4];
                ldsm4(af[0], aq_base + 2u * kk);
                ldsm4(af[1], aq_base + 2u * (16 * PAD_H + kk));
                #pragma unroll
                for (int p = 0; p < 4; p++) {
                    uint32_t bq[4];
                    ldsm4(bq, bkS + 2u * (16 * p * PAD_H + kk));
                    #pragma unroll
                    for (int mi = 0; mi < 2; mi++) {
                        mma_f16(sv[mi][2 * p],     af[mi][0], af[mi][1], af[mi][2], af[mi][3], bq[0], bq[1]);
                        mma_f16(sv[mi][2 * p + 1], af[mi][0], af[mi][1], af[mi][2], af[mi][3], bq[2], bq[3]);
                    }
                }
            }

            // scale by 1/8, then causal mask
            #pragma unroll
            for (int mi = 0; mi < 2; mi++)
                #pragma unroll
                for (int ni = 0; ni < 8; ni++) {
                    sv[mi][ni][0] *= 0.125f; sv[mi][ni][1] *= 0.125f;
                    sv[mi][ni][2] *= 0.125f; sv[mi][ni][3] *= 0.125f;
                }
            if (kt * 64 + 63 > wrow_lo) {
                #pragma unroll
                for (int mi = 0; mi < 2; mi++) {
                    int row0 = wrow_lo + 16 * mi + g;
                    int row1 = row0 + 8;
                    #pragma unroll
                    for (int ni = 0; ni < 8; ni++) {
                        int col = kt * 64 + 8 * ni + 2 * tig;
                        if (col     > row0) sv[mi][ni][0] = -INFINITY;
                        if (col + 1 > row0) sv[mi][ni][1] = -INFINITY;
                        if (col     > row1) sv[mi][ni][2] = -INFINITY;
                        if (col + 1 > row1) sv[mi][ni][3] = -INFINITY;
                    }
                }
            }

            // online softmax
            #pragma unroll
            for (int mi = 0; mi < 2; mi++) {
                float mx0 = sv[mi][0][0], mx1 = sv[mi][0][2];
                #pragma unroll
                for (int ni = 0; ni < 8; ni++) {
                    mx0 = fmaxf(mx0, fmaxf(sv[mi][ni][0], sv[mi][ni][1]));
                    mx1 = fmaxf(mx1, fmaxf(sv[mi][ni][2], sv[mi][ni][3]));
                }
                mx0 = fmaxf(mx0, __shfl_xor_sync(0xffffffffu, mx0, 1));
                mx0 = fmaxf(mx0, __shfl_xor_sync(0xffffffffu, mx0, 2));
                mx1 = fmaxf(mx1, __shfl_xor_sync(0xffffffffu, mx1, 1));
                mx1 = fmaxf(mx1, __shfl_xor_sync(0xffffffffu, mx1, 2));

                float mn0 = fmaxf(m[mi][0], mx0), mn1 = fmaxf(m[mi][1], mx1);
                float al0 = __expf(m[mi][0] - mn0), al1 = __expf(m[mi][1] - mn1);

                __half* pw0 = Ps + (32 * w + 16 * mi + g) * PAD_H + 2 * tig;
                __half* pw1 = pw0 + 8 * PAD_H;
                float r0 = 0.0f, r1 = 0.0f;
                #pragma unroll
                for (int ni = 0; ni < 8; ni++) {
                    float p0 = __expf(sv[mi][ni][0] - mn0);
                    float p1 = __expf(sv[mi][ni][1] - mn0);
                    float p2 = __expf(sv[mi][ni][2] - mn1);
                    float p3 = __expf(sv[mi][ni][3] - mn1);
                    r0 += p0 + p1;
                    r1 += p2 + p3;
                    *(half2*)(pw0 + 8 * ni) = __floats2half2_rn(p0, p1);
                    *(half2*)(pw1 + 8 * ni) = __floats2half2_rn(p2, p3);
                }
                r0 += __shfl_xor_sync(0xffffffffu, r0, 1);
                r0 += __shfl_xor_sync(0xffffffffu, r0, 2);
                r1 += __shfl_xor_sync(0xffffffffu, r1, 1);
                r1 += __shfl_xor_sync(0xffffffffu, r1, 2);

                l[mi][0] = l[mi][0] * al0 + r0;
                l[mi][1] = l[mi][1] * al1 + r1;
                m[mi][0] = mn0;
                m[mi][1] = mn1;

                #pragma unroll
                for (int ni = 0; ni < 8; ni++) {
                    o[mi][ni][0] *= al0; o[mi][ni][1] *= al0;
                    o[mi][ni][2] *= al1; o[mi][ni][3] *= al1;
                }
            }

            __syncwarp();

            // O += P @ V   (V via ldmatrix.trans from [kv][d] tile)
            #pragma unroll
            for (int kk = 0; kk < 64; kk += 16) {
                uint32_t af[2][4];
                ldsm4(af[0], ap_base + 2u * kk);
                ldsm4(af[1], ap_base + 2u * (16 * PAD_H + kk));
                #pragma unroll
                for (int p = 0; p < 4; p++) {
                    uint32_t bq[4];
                    ldsm4t(bq, bvS + 2u * (kk * PAD_H + 16 * p));
                    #pragma unroll
                    for (int mi = 0; mi < 2; mi++) {
                        mma_f16(o[mi][2 * p],     af[mi][0], af[mi][1], af[mi][2], af[mi][3], bq[0], bq[1]);
                        mma_f16(o[mi][2 * p + 1], af[mi][0], af[mi][1], af[mi][2], af[mi][3], bq[2], bq[3]);
                    }
                }
            }
        }
        __syncthreads();
    }

    // epilogue: normalize, write y fp16
    #pragma unroll
    for (int mi = 0; mi < 2; mi++) {
        float inv0 = 1.0f / l[mi][0], inv1 = 1.0f / l[mi][1];
        int row0 = qt * 128 + 32 * w + 16 * mi + g;
        int row1 = row0 + 8;
        #pragma unroll
        for (int ni = 0; ni < 8; ni++) {
            int col = h * HD + 8 * ni + 2 * tig;
            *(half2*)(yh + ((size_t)b * T_SZ + row0) * C_SZ + col) =
                __floats2half2_rn(o[mi][ni][0] * inv0, o[mi][ni][1] * inv0);
            *(half2*)(yh + ((size_t)b * T_SZ + row1) * C_SZ + col) =
                __floats2half2_rn(o[mi][ni][2] * inv1, o[mi][ni][3] * inv1);
        }
    }
}

// ---------------------------------------------------------------------------
// Launch
// ---------------------------------------------------------------------------
extern "C" void kernel_launch(void* const* d_in, const int* in_sizes, int n_in,
                              void* d_out, int out_size)
{
    const float* x      = (const float*)d_in[0];
    const float* w_attn = (const float*)d_in[1];
    const float* b_attn = (const float*)d_in[2];
    const float* w_proj = (const float*)d_in[3];
    const float* b_proj = (const float*)d_in[4];
    float* out = (float*)d_out;

    __half *qkvh = nullptr, *xh = nullptr, *yh = nullptr, *wah = nullptr, *wph = nullptr;
    cudaGetSymbolAddress((void**)&qkvh, g_qkvh);
    cudaGetSymbolAddress((void**)&xh, g_xh);
    cudaGetSymbolAddress((void**)&yh, g_yh);
    cudaGetSymbolAddress((void**)&wah, g_wah);
    cudaGetSymbolAddress((void**)&wph, g_wph);

    cudaFuncSetAttribute(gemm_f16_kernel<__half>,
                         cudaFuncAttributeMaxDynamicSharedMemorySize, G_SMEM_BYTES);
    cudaFuncSetAttribute(gemm_f16_kernel<float>,
                         cudaFuncAttributeMaxDynamicSharedMemorySize, G_SMEM_BYTES);
    cudaFuncSetAttribute(flash_f16_kernel,
                         cudaFuncAttributeMaxDynamicSharedMemorySize, FA_SMEM_BYTES);

    // 0) pre-pass
    cvt_half_kernel<<<(MTOK * C_SZ) / 1024, 256>>>(x, xh);
    {
        dim3 g1(3 * C_SZ / 32, C_SZ / 32);
        transpose_half_kernel<<<g1, 256>>>(w_attn, wah, C_SZ, 3 * C_SZ);
        dim3 g2(C_SZ / 32, C_SZ / 32);
        transpose_half_kernel<<<g2, 256>>>(w_proj, wph, C_SZ, C_SZ);
    }

    // 1) qkv = x @ w_attn + b_attn  -> fp16
    {
        dim3 grid(3 * C_SZ / 128, MTOK / 128);
        gemm_f16_kernel<__half><<<grid, 128, G_SMEM_BYTES>>>(xh, wah, b_attn, qkvh,
                                                             MTOK, 3 * C_SZ, C_SZ);
    }
    // 2) RoPE (fp16 in-place)
    {
        int total = MTOK * NH * 32;
        rope_half_kernel<<<total / 256, 256>>>(qkvh);
    }
    // 3) flash attention -> y fp16
    {
        dim3 grid(T_SZ / 128, NH, B_SZ);
        flash_f16_kernel<<<grid, 128, FA_SMEM_BYTES>>>(qkvh, yh);
    }
    // 4) out = y @ w_proj + b_proj  -> fp32
    {
        dim3 grid(C_SZ / 128, MTOK / 128);
        gemm_f16_kernel<float><<<grid, 128, G_SMEM_BYTES>>>(yh, wph, b_proj, out,
                                                            MTOK, C_SZ, C_SZ);
    }
}

// round 10
// speedup vs baseline: 3.0621x; 1.0106x over previous
#include <cuda_runtime.h>
#include <cuda_fp16.h>
#include <math.h>
#include <stdint.h>

// Problem constants
#define B_SZ 4
#define T_SZ 2048
#define C_SZ 1024
#define NH   16
#define HD   64
#define MTOK (B_SZ * T_SZ)
#define QKV_STRIDE (3 * C_SZ)

// Scratch (device globals — no allocations allowed)
__device__ __half g_qkvh[(size_t)MTOK * QKV_STRIDE]; // 48 MB (fp16, RoPE in-place)
__device__ __half g_xh[(size_t)MTOK * C_SZ];         // 16 MB  x as fp16
__device__ __half g_yh[(size_t)MTOK * C_SZ];         // 16 MB  attention out fp16
__device__ __half g_wah[(size_t)(3 * C_SZ) * C_SZ];  // 6 MB   w_attn^T fp16 [N][K]
__device__ __half g_wph[(size_t)C_SZ * C_SZ];        // 2 MB   w_proj^T fp16 [N][K]

// ---------------------------------------------------------------------------
// Helpers
// ---------------------------------------------------------------------------
__device__ __forceinline__ void mma_f16(float c[4],
    uint32_t a0, uint32_t a1, uint32_t a2, uint32_t a3,
    uint32_t b0, uint32_t b1)
{
    asm volatile(
        "mma.sync.aligned.m16n8k16.row.col.f32.f16.f16.f32 "
        "{%0,%1,%2,%3}, {%4,%5,%6,%7}, {%8,%9}, {%0,%1,%2,%3};"
        : "+f"(c[0]), "+f"(c[1]), "+f"(c[2]), "+f"(c[3])
        : "r"(a0), "r"(a1), "r"(a2), "r"(a3), "r"(b0), "r"(b1));
}

__device__ __forceinline__ void ldsm4(uint32_t r[4], uint32_t saddr) {
    asm volatile("ldmatrix.sync.aligned.m8n8.x4.shared.b16 {%0,%1,%2,%3}, [%4];"
                 : "=r"(r[0]), "=r"(r[1]), "=r"(r[2]), "=r"(r[3]) : "r"(saddr));
}

__device__ __forceinline__ void ldsm4t(uint32_t r[4], uint32_t saddr) {
    asm volatile("ldmatrix.sync.aligned.m8n8.x4.trans.shared.b16 {%0,%1,%2,%3}, [%4];"
                 : "=r"(r[0]), "=r"(r[1]), "=r"(r[2]), "=r"(r[3]) : "r"(saddr));
}

__device__ __forceinline__ uint32_t smem_u32(const void* p) {
    return (uint32_t)__cvta_generic_to_shared(p);
}

__device__ __forceinline__ void cp16s(uint32_t saddr, const void* g) {
    asm volatile("cp.async.cg.shared.global [%0], [%1], 16;" :: "r"(saddr), "l"(g));
}
#define CP_COMMIT() asm volatile("cp.async.commit_group;")

// ---------------------------------------------------------------------------
// Pre-pass: fp32 -> fp16 elementwise
// ---------------------------------------------------------------------------
__global__ __launch_bounds__(256) void cvt_half_kernel(
    const float* __restrict__ src, __half* __restrict__ dst)
{
    int i = (blockIdx.x * 256 + threadIdx.x) * 4;
    float4 v = *(const float4*)(src + i);
    *(half2*)(dst + i)     = __floats2half2_rn(v.x, v.y);
    *(half2*)(dst + i + 2) = __floats2half2_rn(v.z, v.w);
}

// ---------------------------------------------------------------------------
// Pre-pass: transpose+convert weights: src[K][N] fp32 -> dst[N][K] fp16
// ---------------------------------------------------------------------------
__global__ __launch_bounds__(256) void transpose_half_kernel(
    const float* __restrict__ src, __half* __restrict__ dst, int K, int N)
{
    __shared__ __half t[32][34];
    int n0 = blockIdx.x * 32, k0 = blockIdx.y * 32;
    int c = threadIdx.x & 31, r = threadIdx.x >> 5;  // 32 x 8
    #pragma unroll
    for (int i = 0; i < 4; i++)
        t[r + 8 * i][c] = __float2half_rn(src[(size_t)(k0 + r + 8 * i) * N + n0 + c]);
    __syncthreads();
    #pragma unroll
    for (int i = 0; i < 4; i++)
        dst[(size_t)(n0 + r + 8 * i) * K + k0 + c] = t[c][r + 8 * i];
}

// ---------------------------------------------------------------------------
// FP16 GEMM (mma.sync m16n8k16): C[M,N] = Ah[M,K] @ Bh[N,K]^T + bias
//   Tile 128x128, K-chunk 32 halfs, 128 threads = 4 warps, warp tile 64x64.
//   4-stage cp.async pipeline (prefetch distance 3) to cover DRAM latency.
// ---------------------------------------------------------------------------
#define PAD_G 40
#define G_STAGE_H (2 * 128 * PAD_G)          // halfs per stage (A + B)
#define G_NSTAGE 4
#define G_SMEM_BYTES (G_NSTAGE * G_STAGE_H * 2)   // 81920

template <typename OutT>
__global__ __launch_bounds__(128) void gemm_f16_kernel(
    const __half* __restrict__ Ah, const __half* __restrict__ Bh,
    const float* __restrict__ bias, OutT* __restrict__ C,
    int M, int N, int K)
{
    extern __shared__ __half gsm[];
    const uint32_t gsm_sh = smem_u32(gsm);

    const int tid  = threadIdx.x;
    const int wid  = tid >> 5;
    const int lane = tid & 31;
    const int g    = lane >> 2;
    const int tig  = lane & 3;
    const int wm   = (wid & 1) * 64;
    const int wn   = (wid >> 1) * 64;

    const int bm = blockIdx.y * 128;
    const int bn = blockIdx.x * 128;

    const int arow = (lane & 7) + ((lane >> 3) & 1) * 8;
    const int acol = ((lane >> 4) & 1) * 8;
    const int brow = (lane & 7) + ((lane >> 4) & 1) * 8;
    const int bcol = ((lane >> 3) & 1) * 8;
    const uint32_t a_off = 2u * ((wm + arow) * PAD_G + acol);
    const uint32_t b_off = 2u * (128 * PAD_G + (wn + brow) * PAD_G + bcol);

    float acc[4][8][4] = {};

    auto fill = [&](int s, int c) {
        __half* As_ = gsm + s * G_STAGE_H;
        __half* Bs_ = As_ + 128 * PAD_G;
        #pragma unroll
        for (int p = 0; p < 4; p++) {
            int id = tid + 128 * p;
            int r = id >> 2, u = id & 3;
            cp16s(smem_u32(&As_[r * PAD_G + u * 8]),
                  Ah + (size_t)(bm + r) * K + c * 32 + u * 8);
            cp16s(smem_u32(&Bs_[r * PAD_G + u * 8]),
                  Bh + (size_t)(bn + r) * K + c * 32 + u * 8);
        }
        CP_COMMIT();
    };

    const int NC = K >> 5;       // 32 for K=1024
    fill(0, 0);
    fill(1, 1);
    fill(2, 2);

    for (int kt = 0; kt < NC; kt++) {
        if (kt + 3 < NC) {
            // stage (kt+3)&3 was consumed at iteration kt-1 (sync'd below)
            fill((kt + 3) & 3, kt + 3);
            asm volatile("cp.async.wait_group 3;");
        } else {
            int rem = NC - 1 - kt;   // groups pending beyond kt
            if (rem == 2)      asm volatile("cp.async.wait_group 2;");
            else if (rem == 1) asm volatile("cp.async.wait_group 1;");
            else               asm volatile("cp.async.wait_group 0;");
        }
        __syncthreads();

        const uint32_t st = gsm_sh + 2u * ((kt & 3) * G_STAGE_H);
        const uint32_t aB = st + a_off;
        const uint32_t bB = st + b_off;

        #pragma unroll
        for (int kk = 0; kk < 32; kk += 16) {
            uint32_t af[4][4];
            #pragma unroll
            for (int mi = 0; mi < 4; mi++)
                ldsm4(af[mi], aB + 2u * (16 * mi * PAD_G + kk));
            #pragma unroll
            for (int p = 0; p < 4; p++) {
                uint32_t bq[4];
                ldsm4(bq, bB + 2u * (16 * p * PAD_G + kk));
                #pragma unroll
                for (int mi = 0; mi < 4; mi++) {
                    mma_f16(acc[mi][2 * p],     af[mi][0], af[mi][1], af[mi][2], af[mi][3], bq[0], bq[1]);
                    mma_f16(acc[mi][2 * p + 1], af[mi][0], af[mi][1], af[mi][2], af[mi][3], bq[2], bq[3]);
                }
            }
        }
        __syncthreads();
    }

    // epilogue: bias + store (fp32 or fp16)
    #pragma unroll
    for (int ni = 0; ni < 8; ni++) {
        int col = bn + wn + 8 * ni + 2 * tig;
        float bx = bias[col], by = bias[col + 1];
        #pragma unroll
        for (int mi = 0; mi < 4; mi++) {
            int row0 = bm + wm + 16 * mi + g;
            if constexpr (sizeof(OutT) == 4) {
                float2 o0 = {acc[mi][ni][0] + bx, acc[mi][ni][1] + by};
                float2 o1 = {acc[mi][ni][2] + bx, acc[mi][ni][3] + by};
                *(float2*)((float*)C + (size_t)row0 * N + col) = o0;
                *(float2*)((float*)C + (size_t)(row0 + 8) * N + col) = o1;
            } else {
                *(half2*)((__half*)C + (size_t)row0 * N + col) =
                    __floats2half2_rn(acc[mi][ni][0] + bx, acc[mi][ni][1] + by);
                *(half2*)((__half*)C + (size_t)(row0 + 8) * N + col) =
                    __floats2half2_rn(acc[mi][ni][2] + bx, acc[mi][ni][3] + by);
            }
        }
    }
}

// ---------------------------------------------------------------------------
// RoPE on fp16 qkv (fp32 math inside)
// ---------------------------------------------------------------------------
__global__ __launch_bounds__(256) void rope_half_kernel(__half* __restrict__ qkv)
{
    int idx = blockIdx.x * blockDim.x + threadIdx.x;
    int pair = idx & 31;
    int h    = (idx >> 5) & (NH - 1);
    int tok  = idx >> 9;
    int t    = tok & (T_SZ - 1);

    float invf = powf(10000.0f, -(float)pair / 32.0f);
    float ang = (float)t * invf;
    float s, c;
    sincosf(ang, &s, &c);

    size_t base = (size_t)tok * QKV_STRIDE + h * HD;
    __half* q = qkv + base;
    __half* k = qkv + base + C_SZ;

    float q1 = __half2float(q[pair]), q2 = __half2float(q[pair + 32]);
    q[pair]      = __float2half_rn(q1 * c - q2 * s);
    q[pair + 32] = __float2half_rn(q2 * c + q1 * s);
    float k1 = __half2float(k[pair]), k2 = __half2float(k[pair + 32]);
    k[pair]      = __float2half_rn(k1 * c - k2 * s);
    k[pair + 32] = __float2half_rn(k2 * c + k1 * s);
}

// ---------------------------------------------------------------------------
// FP16 flash attention (causal) — unchanged from round 9.
// ---------------------------------------------------------------------------
#define PAD_H 72
#define KV_TILE_H (64 * PAD_H)
#define FQH 0
#define FKH (128 * PAD_H)
#define FVH (FKH + 2 * KV_TILE_H)
#define FPH (FVH + 2 * KV_TILE_H)
#define FA_SMEM_H (FPH + 128 * PAD_H)
#define FA_SMEM_BYTES (FA_SMEM_H * 2)      // 73728

__global__ __launch_bounds__(128) void flash_f16_kernel(
    const __half* __restrict__ qkv, __half* __restrict__ yh)
{
    extern __shared__ __half fsm[];
    __half* Ps = fsm + FPH;
    const uint32_t fsm_sh = smem_u32(fsm);

    const int qt = blockIdx.x;
    const int h  = blockIdx.y;
    const int b  = blockIdx.z;
    const int tid  = threadIdx.x;
    const int w    = tid >> 5;
    const int lane = tid & 31;
    const int g    = lane >> 2;
    const int tig  = lane & 3;

    const int arow = (lane & 7) + ((lane >> 3) & 1) * 8;
    const int acol = ((lane >> 4) & 1) * 8;
    const int brow = (lane & 7) + ((lane >> 4) & 1) * 8;   // non-trans (K)
    const int bcol = ((lane >> 3) & 1) * 8;
    const int vrow = (lane & 7) + ((lane >> 3) & 1) * 8;   // trans (V)
    const int vcol = ((lane >> 4) & 1) * 8;

    const uint32_t aq_base = fsm_sh + 2u * (FQH + (32 * w + arow) * PAD_H + acol);
    const uint32_t ap_base = fsm_sh + 2u * (FPH + (32 * w + arow) * PAD_H + acol);
    const uint32_t bk_base = fsm_sh + 2u * (FKH + brow * PAD_H + bcol);
    const uint32_t bv_base = fsm_sh + 2u * (FVH + vrow * PAD_H + vcol);

    const __half* qbase = qkv + (size_t)b * T_SZ * QKV_STRIDE + h * HD;
    const __half* kbase = qbase + C_SZ;
    const __half* vbase = qbase + 2 * C_SZ;

    auto fill_kv = [&](int s, int kt) {
        __half* Kd = fsm + FKH + s * KV_TILE_H;
        __half* Vd = fsm + FVH + s * KV_TILE_H;
        #pragma unroll
        for (int p = 0; p < 4; p++) {
            int id = tid + 128 * p;
            int r = id >> 3, u = id & 7;
            cp16s(smem_u32(&Kd[r * PAD_H + u * 8]),
                  kbase + (size_t)(kt * 64 + r) * QKV_STRIDE + u * 8);
            cp16s(smem_u32(&Vd[r * PAD_H + u * 8]),
                  vbase + (size_t)(kt * 64 + r) * QKV_STRIDE + u * 8);
        }
        CP_COMMIT();
    };

    {
        __half* Qd = fsm + FQH;
        #pragma unroll
        for (int p = 0; p < 8; p++) {
            int id = tid + 128 * p;
            int r = id >> 3, u = id & 7;
            cp16s(smem_u32(&Qd[r * PAD_H + u * 8]),
                  qbase + (size_t)(qt * 128 + r) * QKV_STRIDE + u * 8);
        }
    }
    fill_kv(0, 0);

    float m[2][2], l[2][2];
    #pragma unroll
    for (int mi = 0; mi < 2; mi++) {
        m[mi][0] = -INFINITY; m[mi][1] = -INFINITY;
        l[mi][0] = 0.0f;      l[mi][1] = 0.0f;
    }
    float o[2][8][4] = {};

    const int wrow_lo = qt * 128 + 32 * w;
    const int ktmax = 2 * qt + 1;

    for (int kt = 0; kt <= ktmax; kt++) {
        const int s = kt & 1;
        if (kt < ktmax) {
            fill_kv(s ^ 1, kt + 1);
            asm volatile("cp.async.wait_group 1;");
        } else {
            asm volatile("cp.async.wait_group 0;");
        }
        __syncthreads();

        const bool active = (kt * 64 <= wrow_lo + 31);
        if (active) {
            const uint32_t bkS = bk_base + 2u * (s * KV_TILE_H);
            const uint32_t bvS = bv_base + 2u * (s * KV_TILE_H);

            float sv[2][8][4] = {};
            #pragma unroll
            for (int kk = 0; kk < 64; kk += 16) {
                uint32_t af[2][4];
                ldsm4(af[0], aq_base + 2u * kk);
                ldsm4(af[1], aq_base + 2u * (16 * PAD_H + kk));
                #pragma unroll
                for (int p = 0; p < 4; p++) {
                    uint32_t bq[4];
                    ldsm4(bq, bkS + 2u * (16 * p * PAD_H + kk));
                    #pragma unroll
                    for (int mi = 0; mi < 2; mi++) {
                        mma_f16(sv[mi][2 * p],     af[mi][0], af[mi][1], af[mi][2], af[mi][3], bq[0], bq[1]);
                        mma_f16(sv[mi][2 * p + 1], af[mi][0], af[mi][1], af[mi][2], af[mi][3], bq[2], bq[3]);
                    }
                }
            }

            #pragma unroll
            for (int mi = 0; mi < 2; mi++)
                #pragma unroll
                for (int ni = 0; ni < 8; ni++) {
                    sv[mi][ni][0] *= 0.125f; sv[mi][ni][1] *= 0.125f;
                    sv[mi][ni][2] *= 0.125f; sv[mi][ni][3] *= 0.125f;
                }
            if (kt * 64 + 63 > wrow_lo) {
                #pragma unroll
                for (int mi = 0; mi < 2; mi++) {
                    int row0 = wrow_lo + 16 * mi + g;
                    int row1 = row0 + 8;
                    #pragma unroll
                    for (int ni = 0; ni < 8; ni++) {
                        int col = kt * 64 + 8 * ni + 2 * tig;
                        if (col     > row0) sv[mi][ni][0] = -INFINITY;
                        if (col + 1 > row0) sv[mi][ni][1] = -INFINITY;
                        if (col     > row1) sv[mi][ni][2] = -INFINITY;
                        if (col + 1 > row1) sv[mi][ni][3] = -INFINITY;
                    }
                }
            }

            #pragma unroll
            for (int mi = 0; mi < 2; mi++) {
                float mx0 = sv[mi][0][0], mx1 = sv[mi][0][2];
                #pragma unroll
                for (int ni = 0; ni < 8; ni++) {
                    mx0 = fmaxf(mx0, fmaxf(sv[mi][ni][0], sv[mi][ni][1]));
                    mx1 = fmaxf(mx1, fmaxf(sv[mi][ni][2], sv[mi][ni][3]));
                }
                mx0 = fmaxf(mx0, __shfl_xor_sync(0xffffffffu, mx0, 1));
                mx0 = fmaxf(mx0, __shfl_xor_sync(0xffffffffu, mx0, 2));
                mx1 = fmaxf(mx1, __shfl_xor_sync(0xffffffffu, mx1, 1));
                mx1 = fmaxf(mx1, __shfl_xor_sync(0xffffffffu, mx1, 2));

                float mn0 = fmaxf(m[mi][0], mx0), mn1 = fmaxf(m[mi][1], mx1);
                float al0 = __expf(m[mi][0] - mn0), al1 = __expf(m[mi][1] - mn1);

                __half* pw0 = Ps + (32 * w + 16 * mi + g) * PAD_H + 2 * tig;
                __half* pw1 = pw0 + 8 * PAD_H;
                float r0 = 0.0f, r1 = 0.0f;
                #pragma unroll
                for (int ni = 0; ni < 8; ni++) {
                    float p0 = __expf(sv[mi][ni][0] - mn0);
                    float p1 = __expf(sv[mi][ni][1] - mn0);
                    float p2 = __expf(sv[mi][ni][2] - mn1);
                    float p3 = __expf(sv[mi][ni][3] - mn1);
                    r0 += p0 + p1;
                    r1 += p2 + p3;
                    *(half2*)(pw0 + 8 * ni) = __floats2half2_rn(p0, p1);
                    *(half2*)(pw1 + 8 * ni) = __floats2half2_rn(p2, p3);
                }
                r0 += __shfl_xor_sync(0xffffffffu, r0, 1);
                r0 += __shfl_xor_sync(0xffffffffu, r0, 2);
                r1 += __shfl_xor_sync(0xffffffffu, r1, 1);
                r1 += __shfl_xor_sync(0xffffffffu, r1, 2);

                l[mi][0] = l[mi][0] * al0 + r0;
                l[mi][1] = l[mi][1] * al1 + r1;
                m[mi][0] = mn0;
                m[mi][1] = mn1;

                #pragma unroll
                for (int ni = 0; ni < 8; ni++) {
                    o[mi][ni][0] *= al0; o[mi][ni][1] *= al0;
                    o[mi][ni][2] *= al1; o[mi][ni][3] *= al1;
                }
            }

            __syncwarp();

            #pragma unroll
            for (int kk = 0; kk < 64; kk += 16) {
                uint32_t af[2][4];
                ldsm4(af[0], ap_base + 2u * kk);
                ldsm4(af[1], ap_base + 2u * (16 * PAD_H + kk));
                #pragma unroll
                for (int p = 0; p < 4; p++) {
                    uint32_t bq[4];
                    ldsm4t(bq, bvS + 2u * (kk * PAD_H + 16 * p));
                    #pragma unroll
                    for (int mi = 0; mi < 2; mi++) {
                        mma_f16(o[mi][2 * p],     af[mi][0], af[mi][1], af[mi][2], af[mi][3], bq[0], bq[1]);
                        mma_f16(o[mi][2 * p + 1], af[mi][0], af[mi][1], af[mi][2], af[mi][3], bq[2], bq[3]);
                    }
                }
            }
        }
        __syncthreads();
    }

    #pragma unroll
    for (int mi = 0; mi < 2; mi++) {
        float inv0 = 1.0f / l[mi][0], inv1 = 1.0f / l[mi][1];
        int row0 = qt * 128 + 32 * w + 16 * mi + g;
        int row1 = row0 + 8;
        #pragma unroll
        for (int ni = 0; ni < 8; ni++) {
            int col = h * HD + 8 * ni + 2 * tig;
            *(half2*)(yh + ((size_t)b * T_SZ + row0) * C_SZ + col) =
                __floats2half2_rn(o[mi][ni][0] * inv0, o[mi][ni][1] * inv0);
            *(half2*)(yh + ((size_t)b * T_SZ + row1) * C_SZ + col) =
                __floats2half2_rn(o[mi][ni][2] * inv1, o[mi][ni][3] * inv1);
        }
    }
}

// ---------------------------------------------------------------------------
// Launch
// ---------------------------------------------------------------------------
extern "C" void kernel_launch(void* const* d_in, const int* in_sizes, int n_in,
                              void* d_out, int out_size)
{
    const float* x      = (const float*)d_in[0];
    const float* w_attn = (const float*)d_in[1];
    const float* b_attn = (const float*)d_in[2];
    const float* w_proj = (const float*)d_in[3];
    const float* b_proj = (const float*)d_in[4];
    float* out = (float*)d_out;

    __half *qkvh = nullptr, *xh = nullptr, *yh = nullptr, *wah = nullptr, *wph = nullptr;
    cudaGetSymbolAddress((void**)&qkvh, g_qkvh);
    cudaGetSymbolAddress((void**)&xh, g_xh);
    cudaGetSymbolAddress((void**)&yh, g_yh);
    cudaGetSymbolAddress((void**)&wah, g_wah);
    cudaGetSymbolAddress((void**)&wph, g_wph);

    cudaFuncSetAttribute(gemm_f16_kernel<__half>,
                         cudaFuncAttributeMaxDynamicSharedMemorySize, G_SMEM_BYTES);
    cudaFuncSetAttribute(gemm_f16_kernel<float>,
                         cudaFuncAttributeMaxDynamicSharedMemorySize, G_SMEM_BYTES);
    cudaFuncSetAttribute(flash_f16_kernel,
                         cudaFuncAttributeMaxDynamicSharedMemorySize, FA_SMEM_BYTES);

    // 0) pre-pass
    cvt_half_kernel<<<(MTOK * C_SZ) / 1024, 256>>>(x, xh);
    {
        dim3 g1(3 * C_SZ / 32, C_SZ / 32);
        transpose_half_kernel<<<g1, 256>>>(w_attn, wah, C_SZ, 3 * C_SZ);
        dim3 g2(C_SZ / 32, C_SZ / 32);
        transpose_half_kernel<<<g2, 256>>>(w_proj, wph, C_SZ, C_SZ);
    }

    // 1) qkv = x @ w_attn + b_attn  -> fp16
    {
        dim3 grid(3 * C_SZ / 128, MTOK / 128);
        gemm_f16_kernel<__half><<<grid, 128, G_SMEM_BYTES>>>(xh, wah, b_attn, qkvh,
                                                             MTOK, 3 * C_SZ, C_SZ);
    }
    // 2) RoPE (fp16 in-place)
    {
        int total = MTOK * NH * 32;
        rope_half_kernel<<<total / 256, 256>>>(qkvh);
    }
    // 3) flash attention -> y fp16
    {
        dim3 grid(T_SZ / 128, NH, B_SZ);
        flash_f16_kernel<<<grid, 128, FA_SMEM_BYTES>>>(qkvh, yh);
    }
    // 4) out = y @ w_proj + b_proj  -> fp32
    {
        dim3 grid(C_SZ / 128, MTOK / 128);
        gemm_f16_kernel<float><<<grid, 128, G_SMEM_BYTES>>>(yh, wph, b_proj, out,
                                                            MTOK, C_SZ, C_SZ);
    }
}